// round 13
// baseline (speedup 1.0000x reference)
#include <cuda_runtime.h>

// Problem constants (fixed shapes from reference setup_inputs)
#define NS   262144      // B*T*C samples
#define NEL  16777216    // B*T*C*F elements for reconstruction loss
#define KK   8           // mixture components
#define DD   8           // latent dim
#define NTRI 36          // D*(D+1)/2 upper-triangular entries
#define MPK  45          // per-k moment slots: gsum(1) + sz(8) + s2(36)

#define LAMBDA_ENERGY 0.1
#define LAMBDA_COV    0.005

// Phase plan: moments runs ALONE on the whole machine (fast, 4x unrolled),
// then energy (1 block/SM, 20K regs) and reconst (5 blocks/SM, 40K regs)
// co-reside: 60K <= 64K register file.
#define MOMENT_BLOCKS  296    // 2/SM, 4x unrolled for MLP
#define RECONST_BLOCKS 740    // 5/SM @32regs
#define ENERGY_BLOCKS  148    // 1/SM
#define DONE_TARGET    (RECONST_BLOCKS + ENERGY_BLOCKS)

// ---------------- device scratch (zero-initialized at module load; the
// finalizing block re-zeroes everything dirtied, so each graph replay starts
// clean without a zeroing launch) ----------------
__device__ double g_mom[KK * MPK];   // [k][0]=gsum, [1..8]=sum(g*z), [9..44]=sum(g*zi*zj)
__device__ double g_reconst;         // sum of squared diffs
__device__ double g_energy;          // sum of per-sample energies
__device__ double g_base;            // lambda_cov*cov_diag (overwritten each run)
__device__ float  g_w2[KK * NTRI];   // quad coeffs (overwritten each run)
__device__ float  g_bv[KK * DD];     // C*mu (overwritten)
__device__ float  g_cst[KK];         // -0.5*mu^T C mu + log(c_k) (overwritten)
__device__ unsigned g_mctr;          // moments last-block counter
__device__ unsigned g_done;          // completion counter (reconst + energy blocks)

// upper-tri row starts for D=8: t(i,j) = TRI_ROW[i] + (j - i), j >= i
__device__ __constant__ int TRI_ROW[8] = {0, 8, 15, 21, 26, 30, 33, 35};

__device__ __forceinline__ float warp_reduce(float v) {
#pragma unroll
    for (int o = 16; o > 0; o >>= 1) v += __shfl_xor_sync(0xFFFFFFFFu, v, o);
    return v;
}

// finalize-if-last: the globally LAST terminal block (reconst or energy)
// writes the scalar and resets all replay state. g_base is valid because
// stats ran in moments' last block, and moments completed before either
// terminal kernel started.
__device__ __forceinline__ void finish_and_maybe_finalize(float* out) {
    __shared__ unsigned s_last;
    if (threadIdx.x == 0) {
        __threadfence();
        unsigned prev = atomicAdd(&g_done, 1u);
        s_last = (prev == (unsigned)(DONE_TARGET - 1)) ? 1u : 0u;
    }
    __syncthreads();
    if (s_last) {
        if (threadIdx.x == 0) {
            __threadfence();
            double rm = g_reconst / (double)NEL;
            double e  = *((volatile double*)&g_energy);
            out[0] = (float)(rm + g_base + LAMBDA_ENERGY * (e / (double)NS));
            g_reconst = 0.0;
            g_energy = 0.0;
            g_done = 0u;
        }
        for (int i = threadIdx.x; i < KK * MPK; i += blockDim.x) g_mom[i] = 0.0;
    }
}

// ---------------- phase 1: GMM moments, whole machine, 4x unrolled ---------
// 8 lanes per sample-slot (one per k); 4 samples' loads front-batched so each
// thread keeps 144B of DRAM traffic in flight (16 warps/SM -> 73KB/SM).
__device__ __forceinline__ void mom_accum(
    float4 z0, float4 z1, float g,
    float& gs, float (&sz)[DD], float (&s2)[NTRI]) {
    float zz[8] = {z0.x, z0.y, z0.z, z0.w, z1.x, z1.y, z1.z, z1.w};
    gs += g;
    float gz[8];
#pragma unroll
    for (int i = 0; i < 8; i++) { gz[i] = g * zz[i]; sz[i] += gz[i]; }
    int t = 0;
#pragma unroll
    for (int i = 0; i < 8; i++)
#pragma unroll
        for (int j = i; j < 8; j++) { s2[t] = fmaf(gz[i], zz[j], s2[t]); t++; }
}

__global__ void __launch_bounds__(256, 2) moments_kernel(
    const float* __restrict__ z, const float* __restrict__ gamma) {
    const int lane = threadIdx.x & 31;
    const int k = lane & 7;
    const int warp = threadIdx.x >> 5;                 // 0..7
    const int slot = (blockIdx.x * 256 + threadIdx.x) >> 3;
    const int stride = (MOMENT_BLOCKS * 256) >> 3;

    float gs = 0.0f;
    float sz[DD];
    float s2[NTRI];
#pragma unroll
    for (int i = 0; i < DD; i++) sz[i] = 0.0f;
#pragma unroll
    for (int t = 0; t < NTRI; t++) s2[t] = 0.0f;

    int n = slot;
    for (; n + 3 * stride < NS; n += 4 * stride) {
        // front-batched: 8x LDG.128 + 4x LDG.32 in flight
        const float* pa = z + (size_t)n * 8;
        const float* pb = z + (size_t)(n + stride) * 8;
        const float* pc = z + (size_t)(n + 2 * stride) * 8;
        const float* pd = z + (size_t)(n + 3 * stride) * 8;
        float4 a0 = *reinterpret_cast<const float4*>(pa);
        float4 a1 = *reinterpret_cast<const float4*>(pa + 4);
        float4 b0 = *reinterpret_cast<const float4*>(pb);
        float4 b1 = *reinterpret_cast<const float4*>(pb + 4);
        float4 c0 = *reinterpret_cast<const float4*>(pc);
        float4 c1 = *reinterpret_cast<const float4*>(pc + 4);
        float4 d0 = *reinterpret_cast<const float4*>(pd);
        float4 d1 = *reinterpret_cast<const float4*>(pd + 4);
        float ga = __ldg(gamma + (size_t)n * 8 + k);
        float gb = __ldg(gamma + (size_t)(n + stride) * 8 + k);
        float gc = __ldg(gamma + (size_t)(n + 2 * stride) * 8 + k);
        float gd = __ldg(gamma + (size_t)(n + 3 * stride) * 8 + k);

        mom_accum(a0, a1, ga, gs, sz, s2);
        mom_accum(b0, b1, gb, gs, sz, s2);
        mom_accum(c0, c1, gc, gs, sz, s2);
        mom_accum(d0, d1, gd, gs, sz, s2);
    }
    for (; n < NS; n += stride) {
        const float* pa = z + (size_t)n * 8;
        float4 a0 = *reinterpret_cast<const float4*>(pa);
        float4 a1 = *reinterpret_cast<const float4*>(pa + 4);
        float g = __ldg(gamma + (size_t)n * 8 + k);
        mom_accum(a0, a1, g, gs, sz, s2);
    }

    const unsigned m = 0xFFFFFFFFu;
    gs += __shfl_xor_sync(m, gs, 8);  gs += __shfl_xor_sync(m, gs, 16);
#pragma unroll
    for (int i = 0; i < DD; i++) {
        sz[i] += __shfl_xor_sync(m, sz[i], 8);
        sz[i] += __shfl_xor_sync(m, sz[i], 16);
    }
#pragma unroll
    for (int t = 0; t < NTRI; t++) {
        s2[t] += __shfl_xor_sync(m, s2[t], 8);
        s2[t] += __shfl_xor_sync(m, s2[t], 16);
    }

    __shared__ float sacc[8][KK * MPK];   // 11.5 KB
    if (lane < 8) {
        float* p = &sacc[warp][k * MPK];
        p[0] = gs;
#pragma unroll
        for (int i = 0; i < DD; i++) p[1 + i] = sz[i];
#pragma unroll
        for (int t = 0; t < NTRI; t++) p[9 + t] = s2[t];
    }
    __syncthreads();

    for (int i = threadIdx.x; i < KK * MPK; i += 256) {
        float v = 0.0f;
#pragma unroll
        for (int w = 0; w < 8; w++) v += sacc[w][i];
        atomicAdd(&g_mom[i], (double)v);
    }

    // ---- last block runs stats inline (warp per component) ----
    __shared__ bool is_last;
    __threadfence();
    __syncthreads();
    if (threadIdx.x == 0) {
        unsigned prev = atomicAdd(&g_mctr, 1u);
        is_last = (prev == (unsigned)(gridDim.x - 1));
        if (is_last) g_mctr = 0u;      // reset for next replay
    }
    __syncthreads();
    if (!is_last) return;
    __threadfence();                    // acquire all g_mom writes

    {
        const int w = threadIdx.x >> 5;        // component k
        const int r = threadIdx.x & 31;        // lane; rows live in lanes 0..7
        __shared__ float s_cd[8];

        const double* mo = g_mom + w * MPK;
        const float gsf = (float)mo[0];
        const float rgs = 1.0f / gsf;

        float mu[8];
#pragma unroll
        for (int j = 0; j < 8; j++) mu[j] = (float)mo[1 + j] * rgs;

        float ar[8], ir[8];
        float cd = 0.0f;
        if (r < 8) {
#pragma unroll
            for (int j = 0; j < 8; j++) {
                int i0 = r < j ? r : j;
                int j0 = r < j ? j : r;
                int t = TRI_ROW[i0] + (j0 - i0);
                ar[j] = fmaf(-mu[r], mu[j], (float)mo[9 + t] * rgs);
                ir[j] = (r == j) ? 1.0f : 0.0f;
            }
            ar[r] += 1e-12f;                   // EPS*I, matches reference
            cd = 1.0f / ar[r];
        } else {
#pragma unroll
            for (int j = 0; j < 8; j++) { ar[j] = (r == j + 24) ? 1.0f : 0.0f; ir[j] = 0.0f; }
        }

        float det = 1.0f;
#pragma unroll
        for (int p = 0; p < 8; p++) {
            float piv = __shfl_sync(m, ar[p], p);
            det *= piv;
            float rc = 1.0f / piv;
            float par[8], pir[8];
#pragma unroll
            for (int j = 0; j < 8; j++) par[j] = __shfl_sync(m, ar[j], p) * rc;
#pragma unroll
            for (int j = 0; j < 8; j++) pir[j] = __shfl_sync(m, ir[j], p) * rc;
            float f = ar[p];
            if (r == p) {
#pragma unroll
                for (int j = 0; j < 8; j++) { ar[j] = par[j]; ir[j] = pir[j]; }
            } else {
#pragma unroll
                for (int j = 0; j < 8; j++) {
                    ar[j] = fmaf(-f, par[j], ar[j]);
                    ir[j] = fmaf(-f, pir[j], ir[j]);
                }
            }
        }

        float cstp = 0.0f;
        if (r < 8) {
#pragma unroll
            for (int j = 0; j < 8; j++) {
                if (j >= r) {
                    int t = TRI_ROW[r] + (j - r);
                    g_w2[w * NTRI + t] = (j == r) ? (-0.5f * ir[r]) : (-ir[j]);
                }
            }
            float b = 0.0f;
#pragma unroll
            for (int j = 0; j < 8; j++) b = fmaf(ir[j], mu[j], b);
            g_bv[w * DD + r] = b;
            cstp = b * mu[r];
        }
#pragma unroll
        for (int o = 4; o > 0; o >>= 1) {
            cstp += __shfl_xor_sync(m, cstp, o);
            cd   += __shfl_xor_sync(m, cd, o);
        }
        if (r == 0) {
            float phi = gsf * (1.0f / (float)NS);
            float ck = phi / (39.478417604357434f * sqrtf(sqrtf(det)));
            g_cst[w] = -0.5f * cstp + logf(ck);
            s_cd[w] = cd;
        }
        __syncthreads();
        if (threadIdx.x == 0) {
            float cdt = 0.0f;
#pragma unroll
            for (int i = 0; i < 8; i++) cdt += s_cd[i];
            g_base = LAMBDA_COV * (double)cdt;   // reconst term added at finalize
        }
    }
}

// ---------------- phase 2a (main): reconstruction sum (pure HBM stream) ----
__global__ void __launch_bounds__(256, 5) reconst_kernel(
    const float4* __restrict__ x, const float4* __restrict__ xh,
    float* __restrict__ out) {
    const int n4 = NEL / 4;
    float acc0 = 0.0f, acc1 = 0.0f;
    int i = blockIdx.x * 256 + threadIdx.x;
    const int stride = RECONST_BLOCKS * 256;
    for (; i + stride < n4; i += 2 * stride) {
        float4 a0 = x[i], b0 = xh[i];
        float4 a1 = x[i + stride], b1 = xh[i + stride];
        float d;
        d = b0.x - a0.x; acc0 = fmaf(d, d, acc0);
        d = b0.y - a0.y; acc0 = fmaf(d, d, acc0);
        d = b0.z - a0.z; acc0 = fmaf(d, d, acc0);
        d = b0.w - a0.w; acc0 = fmaf(d, d, acc0);
        d = b1.x - a1.x; acc1 = fmaf(d, d, acc1);
        d = b1.y - a1.y; acc1 = fmaf(d, d, acc1);
        d = b1.z - a1.z; acc1 = fmaf(d, d, acc1);
        d = b1.w - a1.w; acc1 = fmaf(d, d, acc1);
    }
    for (; i < n4; i += stride) {
        float4 a = x[i], b = xh[i];
        float d;
        d = b.x - a.x; acc0 = fmaf(d, d, acc0);
        d = b.y - a.y; acc0 = fmaf(d, d, acc0);
        d = b.z - a.z; acc0 = fmaf(d, d, acc0);
        d = b.w - a.w; acc0 = fmaf(d, d, acc0);
    }
    __shared__ float red[8];
    float v = warp_reduce(acc0 + acc1);
    int lane = threadIdx.x & 31, wid = threadIdx.x >> 5;
    if (lane == 0) red[wid] = v;
    __syncthreads();
    if (threadIdx.x == 0) {
        float s = 0.0f;
#pragma unroll
        for (int w = 0; w < 8; w++) s += red[w];
        atomicAdd(&g_reconst, (double)s);
    }
    finish_and_maybe_finalize(out);
}

// ---------------- phase 2b (side): energy, 1 block/SM, co-resident ---------
__global__ void __launch_bounds__(256, 2) energy_kernel(const float* __restrict__ z,
                                                        float* __restrict__ out) {
    const int lane = threadIdx.x & 31;
    const int k = lane & 7;

    float w[NTRI], bv[DD], cst;
#pragma unroll
    for (int t = 0; t < NTRI; t++) w[t] = g_w2[k * NTRI + t];
#pragma unroll
    for (int i = 0; i < DD; i++) bv[i] = g_bv[k * DD + i];
    cst = g_cst[k];

    const int slot = (blockIdx.x * blockDim.x + threadIdx.x) >> 3;
    const int stride = (gridDim.x * blockDim.x) >> 3;
    const unsigned m = 0xFFFFFFFFu;

    float acc = 0.0f;
    int n = slot;
    for (; n + stride < NS; n += 2 * stride) {
        float4 a0 = *reinterpret_cast<const float4*>(z + (size_t)n * 8);
        float4 a1 = *reinterpret_cast<const float4*>(z + (size_t)n * 8 + 4);
        float4 b0 = *reinterpret_cast<const float4*>(z + (size_t)(n + stride) * 8);
        float4 b1 = *reinterpret_cast<const float4*>(z + (size_t)(n + stride) * 8 + 4);

        {
            float zz[8] = {a0.x, a0.y, a0.z, a0.w, a1.x, a1.y, a1.z, a1.w};
            float q = cst;
            int t = 0;
#pragma unroll
            for (int i = 0; i < 8; i++) {
                float row = bv[i];
#pragma unroll
                for (int j = i; j < 8; j++) { row = fmaf(w[t], zz[j], row); t++; }
                q = fmaf(zz[i], row, q);
            }
            float e = __expf(q);
            e += __shfl_xor_sync(m, e, 1);
            e += __shfl_xor_sync(m, e, 2);
            e += __shfl_xor_sync(m, e, 4);
            if (k == 0) acc += -__logf(e + 1e-12f);
        }
        {
            float zz[8] = {b0.x, b0.y, b0.z, b0.w, b1.x, b1.y, b1.z, b1.w};
            float q = cst;
            int t = 0;
#pragma unroll
            for (int i = 0; i < 8; i++) {
                float row = bv[i];
#pragma unroll
                for (int j = i; j < 8; j++) { row = fmaf(w[t], zz[j], row); t++; }
                q = fmaf(zz[i], row, q);
            }
            float e = __expf(q);
            e += __shfl_xor_sync(m, e, 1);
            e += __shfl_xor_sync(m, e, 2);
            e += __shfl_xor_sync(m, e, 4);
            if (k == 0) acc += -__logf(e + 1e-12f);
        }
    }
    for (; n < NS; n += stride) {
        float4 a0 = *reinterpret_cast<const float4*>(z + (size_t)n * 8);
        float4 a1 = *reinterpret_cast<const float4*>(z + (size_t)n * 8 + 4);
        float zz[8] = {a0.x, a0.y, a0.z, a0.w, a1.x, a1.y, a1.z, a1.w};
        float q = cst;
        int t = 0;
#pragma unroll
        for (int i = 0; i < 8; i++) {
            float row = bv[i];
#pragma unroll
            for (int j = i; j < 8; j++) { row = fmaf(w[t], zz[j], row); t++; }
            q = fmaf(zz[i], row, q);
        }
        float e = __expf(q);
        e += __shfl_xor_sync(m, e, 1);
        e += __shfl_xor_sync(m, e, 2);
        e += __shfl_xor_sync(m, e, 4);
        if (k == 0) acc += -__logf(e + 1e-12f);
    }

    __shared__ float red[8];
    float v = warp_reduce(acc);
    int wid = threadIdx.x >> 5;
    if (lane == 0) red[wid] = v;
    __syncthreads();
    if (threadIdx.x == 0) {
        float s = 0.0f;
#pragma unroll
        for (int i = 0; i < 8; i++) s += red[i];
        atomicAdd(&g_energy, (double)s);
    }
    finish_and_maybe_finalize(out);
}

// ---------------- launch: moments first (whole machine), then fork ---------
static cudaStream_t s_side = nullptr;
static cudaEvent_t s_mdone = nullptr, s_join = nullptr;

extern "C" void kernel_launch(void* const* d_in, const int* in_sizes, int n_in,
                              void* d_out, int out_size) {
    const float* x     = (const float*)d_in[0];
    const float* xh    = (const float*)d_in[1];
    const float* z     = (const float*)d_in[2];
    const float* gamma = (const float*)d_in[3];
    float* out = (float*)d_out;

    if (s_side == nullptr) {
        cudaStreamCreateWithFlags(&s_side, cudaStreamNonBlocking);
        cudaEventCreateWithFlags(&s_mdone, cudaEventDisableTiming);
        cudaEventCreateWithFlags(&s_join, cudaEventDisableTiming);
    }

    // phase 1: moments alone on the whole machine (fast, 4x unrolled)
    moments_kernel<<<MOMENT_BLOCKS, 256>>>(z, gamma);
    cudaEventRecord(s_mdone, 0);
    // phase 2: energy (1/SM) and reconst (5/SM) genuinely co-resident
    cudaStreamWaitEvent(s_side, s_mdone, 0);
    energy_kernel<<<ENERGY_BLOCKS, 256, 0, s_side>>>(z, out);
    reconst_kernel<<<RECONST_BLOCKS, 256>>>((const float4*)x, (const float4*)xh, out);
    // join so the harness's stream sees side-stream completion
    cudaEventRecord(s_join, s_side);
    cudaStreamWaitEvent(0, s_join, 0);
}